// round 1
// baseline (speedup 1.0000x reference)
#include <cuda_runtime.h>
#include <cstdint>

#define N_USERS 50000
#define N_ITEMS 20000
#define N_EDGES_C 1000000
#define NR 5
#define F 64
#define HID 64
#define KDIM 320   // NR * F

// -------- scratch (device globals; no allocation allowed) --------
__device__ float g_acc_u[(size_t)N_USERS * NR * F];   // 64 MB
__device__ float g_acc_v[(size_t)N_ITEMS * NR * F];   // 25.6 MB
__device__ float g_cnt_u[N_USERS * NR];               // 1 MB
__device__ float g_cnt_v[N_ITEMS * NR];               // 0.4 MB

// -------- phase 0: zero scratch --------
__global__ void zero_kernel() {
    size_t tid = (size_t)blockIdx.x * blockDim.x + threadIdx.x;
    size_t stride = (size_t)gridDim.x * blockDim.x;
    float4 z = make_float4(0.f, 0.f, 0.f, 0.f);
    size_t n_u = (size_t)N_USERS * NR * F / 4;
    float4* pu = reinterpret_cast<float4*>(g_acc_u);
    for (size_t i = tid; i < n_u; i += stride) pu[i] = z;
    size_t n_v = (size_t)N_ITEMS * NR * F / 4;
    float4* pv = reinterpret_cast<float4*>(g_acc_v);
    for (size_t i = tid; i < n_v; i += stride) pv[i] = z;
    size_t n_cu = (size_t)N_USERS * NR / 4;
    float4* pcu = reinterpret_cast<float4*>(g_cnt_u);
    for (size_t i = tid; i < n_cu; i += stride) pcu[i] = z;
    size_t n_cv = (size_t)N_ITEMS * NR / 4;
    float4* pcv = reinterpret_cast<float4*>(g_cnt_v);
    for (size_t i = tid; i < n_cv; i += stride) pcv[i] = z;
}

// -------- phase 1: edge scatter with vector reductions --------
__device__ __forceinline__ void red_add_v4(float* p, float4 v) {
    asm volatile("red.global.add.v4.f32 [%0], {%1, %2, %3, %4};"
                 :: "l"(p), "f"(v.x), "f"(v.y), "f"(v.z), "f"(v.w)
                 : "memory");
}

#define EDGES_PER_WARP 4

__global__ void edge_kernel(const int* __restrict__ u_s,
                            const int* __restrict__ v_s,
                            const int* __restrict__ rate,
                            const float* __restrict__ x_user,
                            const float* __restrict__ x_item) {
    int warp_id = (blockIdx.x * blockDim.x + threadIdx.x) >> 5;
    int lane = threadIdx.x & 31;
    int half = lane >> 4;       // 0: h_u direction, 1: h_v direction
    int l16  = lane & 15;       // float4 slot within the 64-float row

    int e0 = warp_id * EDGES_PER_WARP;
    #pragma unroll
    for (int i = 0; i < EDGES_PER_WARP; i++) {
        int e = e0 + i;
        if (e >= N_EDGES_C) return;
        int u = u_s[e];
        int v = v_s[e];
        int r = rate[e];

        const float4* src;
        float* dst;
        if (half == 0) {
            // aggregate item features into user accumulator
            src = reinterpret_cast<const float4*>(x_item + (size_t)v * F);
            dst = g_acc_u + ((size_t)u * NR + r) * F;
        } else {
            // aggregate user features into item accumulator
            src = reinterpret_cast<const float4*>(x_user + (size_t)u * F);
            dst = g_acc_v + ((size_t)v * NR + r) * F;
        }
        float4 val = src[l16];
        red_add_v4(dst + (size_t)l16 * 4, val);

        if (lane == 0)  atomicAdd(&g_cnt_u[u * NR + r], 1.0f);
        if (lane == 16) atomicAdd(&g_cnt_v[v * NR + r], 1.0f);
    }
}

// -------- phase 2: out = (acc * 1/max(cnt,1)) @ Wflat  (M x 320 @ 320 x 64) --------
#define BM 128
#define KK 32

__global__ __launch_bounds__(256) void out_gemm(int which,
                                                const float* __restrict__ W,
                                                float* __restrict__ out) {
    const float* __restrict__ A   = which ? g_acc_v : g_acc_u;
    const float* __restrict__ cnt = which ? g_cnt_v : g_cnt_u;
    const int M = which ? N_ITEMS : N_USERS;

    __shared__ float As[BM][KK + 1];   // +1 pad: conflict-free broadcast reads
    __shared__ float Bs[KK][HID];

    int tid = threadIdx.x;             // 256 threads
    int tx = tid & 15;                 // output cols tx*4 .. tx*4+3
    int ty = tid >> 4;                 // output rows ty*8 .. ty*8+7
    int rowBase = blockIdx.x * BM;

    // A-tile loader mapping: each thread loads 16 floats (one half-row of a chunk)
    int lrow  = tid >> 1;              // 0..127
    int lkoff = (tid & 1) * 16;        // 0 or 16

    float acc[8][4];
    #pragma unroll
    for (int i = 0; i < 8; i++)
        #pragma unroll
        for (int j = 0; j < 4; j++) acc[i][j] = 0.f;

    for (int k0 = 0; k0 < KDIM; k0 += KK) {
        // ---- load + scale A chunk [128 x 32] ----
        {
            int grow = rowBase + lrow;
            if (grow < M) {
                float c = cnt[grow * NR + (k0 >> 6)];       // rating block = k0/64
                float invc = 1.0f / fmaxf(c, 1.0f);
                const float4* ap = reinterpret_cast<const float4*>(
                    A + (size_t)grow * KDIM + k0 + lkoff);
                #pragma unroll
                for (int j = 0; j < 4; j++) {
                    float4 val = ap[j];
                    int kk = lkoff + j * 4;
                    As[lrow][kk + 0] = val.x * invc;
                    As[lrow][kk + 1] = val.y * invc;
                    As[lrow][kk + 2] = val.z * invc;
                    As[lrow][kk + 3] = val.w * invc;
                }
            } else {
                #pragma unroll
                for (int j = 0; j < 4; j++) {
                    int kk = lkoff + j * 4;
                    As[lrow][kk + 0] = 0.f;
                    As[lrow][kk + 1] = 0.f;
                    As[lrow][kk + 2] = 0.f;
                    As[lrow][kk + 3] = 0.f;
                }
            }
        }
        // ---- load W chunk [32 x 64] = 512 float4, 2 per thread ----
        {
            const float4* wp = reinterpret_cast<const float4*>(W + (size_t)k0 * HID);
            float4* bsp = reinterpret_cast<float4*>(&Bs[0][0]);
            bsp[tid]       = wp[tid];
            bsp[tid + 256] = wp[tid + 256];
        }
        __syncthreads();

        // ---- compute ----
        #pragma unroll 8
        for (int k = 0; k < KK; k++) {
            float4 b = *reinterpret_cast<const float4*>(&Bs[k][tx * 4]);
            #pragma unroll
            for (int i = 0; i < 8; i++) {
                float a = As[ty * 8 + i][k];
                acc[i][0] += a * b.x;
                acc[i][1] += a * b.y;
                acc[i][2] += a * b.z;
                acc[i][3] += a * b.w;
            }
        }
        __syncthreads();
    }

    #pragma unroll
    for (int i = 0; i < 8; i++) {
        int row = rowBase + ty * 8 + i;
        if (row < M) {
            float4 o = make_float4(acc[i][0], acc[i][1], acc[i][2], acc[i][3]);
            *reinterpret_cast<float4*>(out + (size_t)row * HID + tx * 4) = o;
        }
    }
}

// -------- launch --------
extern "C" void kernel_launch(void* const* d_in, const int* in_sizes, int n_in,
                              void* d_out, int out_size) {
    const int*   u_s    = (const int*)d_in[0];
    const int*   v_s    = (const int*)d_in[1];
    const int*   rate   = (const int*)d_in[2];
    const float* x_user = (const float*)d_in[3];
    const float* x_item = (const float*)d_in[4];
    const float* weight = (const float*)d_in[5];
    float* out = (float*)d_out;

    (void)in_sizes; (void)n_in; (void)out_size;

    zero_kernel<<<4096, 256>>>();

    // 1M edges, 1 warp per EDGES_PER_WARP edges, 8 warps per block
    int n_warps = (N_EDGES_C + EDGES_PER_WARP - 1) / EDGES_PER_WARP;
    int n_blocks = (n_warps + 7) / 8;
    edge_kernel<<<n_blocks, 256>>>(u_s, v_s, rate, x_user, x_item);

    out_gemm<<<(N_USERS + BM - 1) / BM, 256>>>(0, weight, out);
    out_gemm<<<(N_ITEMS + BM - 1) / BM, 256>>>(1, weight, out + (size_t)N_USERS * HID);
}